// round 11
// baseline (speedup 1.0000x reference)
#include <cuda_runtime.h>
#include <cstdint>

#define ALPHA 0.2f

// Problem constants (fixed by the dataset)
#define B_   8
#define N_   1024
#define CIN  256
#define COUT 256
#define R_   4
#define H_   4

// Scratch (static device arrays; no runtime allocation)
__device__ __align__(16) float    g_F   [R_ * B_ * N_ * COUT];  // 32 MB tf32-rounded
__device__ __align__(16) float    g_part[R_ * B_ * N_ * COUT];  // 32 MB per-relation out
__device__ __align__(16) float2   g_eli [R_ * B_ * N_ * H_];
__device__ __align__(16) float2   g_elj [R_ * B_ * N_ * H_];
__device__ __align__(16) unsigned g_bits[B_ * R_ * N_ * 32];    // 4 MB adjacency bitmaps

// ---------------------------------------------------------------------------
// helpers
// ---------------------------------------------------------------------------
__device__ __forceinline__ unsigned cvt_tf32(float f) {
    unsigned u;
    asm("cvt.rna.tf32.f32 %0, %1;" : "=r"(u) : "f"(f));
    return u;
}

__device__ __forceinline__ void mma_tf32(float* c,
                                         unsigned a0, unsigned a1, unsigned a2, unsigned a3,
                                         unsigned b0, unsigned b1) {
    asm volatile("mma.sync.aligned.m16n8k8.row.col.f32.tf32.tf32.f32 "
                 "{%0,%1,%2,%3}, {%4,%5,%6,%7}, {%8,%9}, {%0,%1,%2,%3};"
                 : "+f"(c[0]), "+f"(c[1]), "+f"(c[2]), "+f"(c[3])
                 : "r"(a0), "r"(a1), "r"(a2), "r"(a3), "r"(b0), "r"(b1));
}

__device__ __forceinline__ void cpa16(uint32_t dst, const void* src) {
    asm volatile("cp.async.cg.shared.global [%0], [%1], 16;" :: "r"(dst), "l"(src));
}
#define CP_COMMIT() asm volatile("cp.async.commit_group;")
#define CP_WAIT(n)  asm volatile("cp.async.wait_group %0;" :: "n"(n))

// ---------------------------------------------------------------------------
// Kernel 0: pack adjacency into per-relation bitmasks (reads adj ONCE).
// g_bits layout: [b][r][i][jw]  (jw = j/32)
// ---------------------------------------------------------------------------
__global__ __launch_bounds__(256)
void pack_kernel(const int* __restrict__ adj)
{
    const int idx = blockIdx.x * 256 + threadIdx.x;   // < B*N*32
    const int jw = idx & 31;
    const int i  = (idx >> 5) & (N_ - 1);
    const int b  = idx >> 15;

    const int4* ap = (const int4*)adj + ((size_t)(b * N_ + i) * N_ + jw * 32);
    unsigned w0 = 0, w1 = 0, w2 = 0, w3 = 0;
#pragma unroll 8
    for (int jj = 0; jj < 32; jj++) {
        int4 v = ap[jj];
        w0 |= (unsigned)(v.x != 0) << jj;
        w1 |= (unsigned)(v.y != 0) << jj;
        w2 |= (unsigned)(v.z != 0) << jj;
        w3 |= (unsigned)(v.w != 0) << jj;
    }
    const size_t base = ((size_t)b * R_ * N_ + i) * 32 + jw;
    g_bits[base + (size_t)0 * N_ * 32] = w0;
    g_bits[base + (size_t)1 * N_ * 32] = w1;
    g_bits[base + (size_t)2 * N_ * 32] = w2;
    g_bits[base + (size_t)3 * N_ * 32] = w3;
}

// ---------------------------------------------------------------------------
// Kernel 1: F[r,b] = X[b] @ W[r] via tf32 mma.sync, li/lj fused in epilogue.
// ---------------------------------------------------------------------------
#define PADK 20
#define PADN 136

__global__ __launch_bounds__(256, 2)
void gemm_kernel(const float* __restrict__ X, const float* __restrict__ W,
                 const float* __restrict__ a)
{
    const int rb = blockIdx.z, r = rb >> 3, b = rb & 7;
    const float* Ag = X + (size_t)b * N_ * CIN;
    const float* Bg = W + (size_t)r * CIN * COUT;
    float* out = g_F + (size_t)rb * N_ * COUT;
    const int m0 = blockIdx.x * 128, n0 = blockIdx.y * 128;

    __shared__ float As[2][128 * PADK];
    __shared__ float Bs[2][16 * PADN];

    const int tid = threadIdx.x, warp = tid >> 5, lane = tid & 31;
    const int wm = (warp & 3) * 32, wn = (warp >> 2) * 64;
    const int g = lane >> 2, t = lane & 3;

    const uint32_t sA = (uint32_t)__cvta_generic_to_shared(&As[0][0]);
    const uint32_t sB = (uint32_t)__cvta_generic_to_shared(&Bs[0][0]);

    float acc[2][8][4];
#pragma unroll
    for (int mt = 0; mt < 2; mt++)
#pragma unroll
        for (int nt = 0; nt < 8; nt++)
#pragma unroll
            for (int k = 0; k < 4; k++) acc[mt][nt][k] = 0.f;

    auto stage = [&](int s) {
        const int buf = s & 1, k0 = s * 16;
#pragma unroll
        for (int i = 0; i < 2; i++) {
            int idx = tid * 2 + i;
            int row = idx >> 2, c = idx & 3;
            cpa16(sA + (uint32_t)(buf * (128 * PADK) + row * PADK + c * 4) * 4,
                  Ag + (size_t)(m0 + row) * CIN + k0 + c * 4);
        }
#pragma unroll
        for (int i = 0; i < 2; i++) {
            int idx = tid * 2 + i;
            int row = idx >> 5, c = idx & 31;
            cpa16(sB + (uint32_t)(buf * (16 * PADN) + row * PADN + c * 4) * 4,
                  Bg + (size_t)(k0 + row) * COUT + n0 + c * 4);
        }
        CP_COMMIT();
    };

    stage(0);
    for (int s = 0; s < 16; s++) {
        if (s + 1 < 16) { stage(s + 1); CP_WAIT(1); } else { CP_WAIT(0); }
        __syncthreads();
        const float* Ab = As[s & 1];
        const float* Bb = Bs[s & 1];
#pragma unroll
        for (int kk = 0; kk < 16; kk += 8) {
            unsigned af[2][4], bf[8][2];
#pragma unroll
            for (int mt = 0; mt < 2; mt++) {
                int rowb = wm + mt * 16 + g;
                af[mt][0] = cvt_tf32(Ab[rowb * PADK + kk + t]);
                af[mt][1] = cvt_tf32(Ab[(rowb + 8) * PADK + kk + t]);
                af[mt][2] = cvt_tf32(Ab[rowb * PADK + kk + 4 + t]);
                af[mt][3] = cvt_tf32(Ab[(rowb + 8) * PADK + kk + 4 + t]);
            }
#pragma unroll
            for (int nt = 0; nt < 8; nt++) {
                int col = wn + nt * 8 + g;
                bf[nt][0] = cvt_tf32(Bb[(kk + t) * PADN + col]);
                bf[nt][1] = cvt_tf32(Bb[(kk + 4 + t) * PADN + col]);
            }
#pragma unroll
            for (int mt = 0; mt < 2; mt++)
#pragma unroll
                for (int nt = 0; nt < 8; nt++)
                    mma_tf32(acc[mt][nt], af[mt][0], af[mt][1], af[mt][2], af[mt][3],
                             bf[nt][0], bf[nt][1]);
        }
        __syncthreads();
    }

    // fused li/lj epilogue (warp tile covers head h fully)
    {
        const int h = blockIdx.y * 2 + (warp >> 2);
        const float2* al2 = (const float2*)(a + (size_t)(r * H_ + h) * 128);
        const float2* ar2 = al2 + 32;
#pragma unroll
        for (int mt = 0; mt < 2; mt++) {
            float sliA = 0.f, sliB = 0.f, sljA = 0.f, sljB = 0.f;
#pragma unroll
            for (int nt = 0; nt < 8; nt++) {
                float2 al = al2[nt * 4 + t];
                float2 ar = ar2[nt * 4 + t];
                sliA += acc[mt][nt][0] * al.x + acc[mt][nt][1] * al.y;
                sliB += acc[mt][nt][2] * al.x + acc[mt][nt][3] * al.y;
                sljA += acc[mt][nt][0] * ar.x + acc[mt][nt][1] * ar.y;
                sljB += acc[mt][nt][2] * ar.x + acc[mt][nt][3] * ar.y;
            }
#pragma unroll
            for (int d = 1; d < 4; d <<= 1) {
                sliA += __shfl_xor_sync(0xffffffffu, sliA, d);
                sliB += __shfl_xor_sync(0xffffffffu, sliB, d);
                sljA += __shfl_xor_sync(0xffffffffu, sljA, d);
                sljB += __shfl_xor_sync(0xffffffffu, sljB, d);
            }
            if (t == 0) {
                const int row = m0 + wm + mt * 16 + g;
                const size_t base = ((size_t)(r * B_ + b) * N_ + row) * H_ + h;
                g_eli[base] = make_float2(__expf(sliA), __expf(ALPHA * sliA));
                g_elj[base] = make_float2(__expf(sljA), __expf(ALPHA * sljA));
                g_eli[base + 8 * H_] = make_float2(__expf(sliB), __expf(ALPHA * sliB));
                g_elj[base + 8 * H_] = make_float2(__expf(sljB), __expf(ALPHA * sljB));
            }
        }
    }

    // store F pre-rounded to tf32
#pragma unroll
    for (int mt = 0; mt < 2; mt++) {
        int row = m0 + wm + mt * 16 + g;
#pragma unroll
        for (int nt = 0; nt < 8; nt++) {
            int col = n0 + wn + nt * 8 + 2 * t;
            float2 v0 = make_float2(__uint_as_float(cvt_tf32(acc[mt][nt][0])),
                                    __uint_as_float(cvt_tf32(acc[mt][nt][1])));
            float2 v1 = make_float2(__uint_as_float(cvt_tf32(acc[mt][nt][2])),
                                    __uint_as_float(cvt_tf32(acc[mt][nt][3])));
            *(float2*)(out + (size_t)row * COUT + col) = v0;
            *(float2*)(out + (size_t)(row + 8) * COUT + col) = v1;
        }
    }
}

// ---------------------------------------------------------------------------
// Kernel 2: attention for ONE relation per block (r-split -> no outacc regs).
// grid 512 = (r, b, tile); block 256 thr = 8 warps = (mi 0..1) x (h 0..3),
// warp tile 32i x 64c.  Writes normalized per-relation result to g_part.
// ---------------------------------------------------------------------------
#define FSTR 264            // F smem row stride (floats)
#define FBUF (64 * FSTR)    // floats per buffer

__global__ __launch_bounds__(256, 1)
void attn_kernel(float* __restrict__ dummy)
{
    extern __shared__ float smem[];
    float*    Fs   = smem;                                // 2 buffers of 64*FSTR
    float2*   Elj  = (float2*)(Fs + 2 * FBUF);            // [1024][4]
    unsigned* bits = (unsigned*)(Elj + N_ * H_);          // [64][32]

    const uint32_t sF = (uint32_t)__cvta_generic_to_shared(Fs);

    const int tid = threadIdx.x;
    const int i0 = (blockIdx.x & 15) * 64;
    const int b  = (blockIdx.x >> 4) & 7;
    const int r  = blockIdx.x >> 7;

    // stage bitmap (8 KB) + Elj (32 KB) for this (r,b)
    {
        const uint4* bsrc = (const uint4*)(g_bits + (((size_t)b * R_ + r) * N_ + i0) * 32);
        uint4* bdst = (uint4*)bits;
#pragma unroll
        for (int k = 0; k < 2; k++) bdst[k * 256 + tid] = bsrc[k * 256 + tid];
        const float4* src = (const float4*)(g_elj + (size_t)(r * B_ + b) * N_ * H_);
        float4* dst = (float4*)Elj;
#pragma unroll
        for (int k = 0; k < 8; k++) dst[k * 256 + tid] = src[k * 256 + tid];
    }

    const int warp = tid >> 5, lane = tid & 31;
    const int h = warp & 3, mi = warp >> 2;               // mi in {0,1}
    const int g = lane >> 2, t = lane & 3;
    const int r0 = mi * 32 + g, r1 = r0 + 8, r2 = r0 + 16, r3 = r0 + 24;
    const int nb = h * 64;

    const float* Fb = g_F + (size_t)(r * B_ + b) * N_ * COUT;

    auto stageF = [&](int jc) {
        const int buf = jc & 1;
        const float* src = Fb + (size_t)jc * 64 * COUT;
        const uint32_t dst = sF + (uint32_t)(buf * FBUF) * 4;
#pragma unroll
        for (int k = 0; k < 16; k++) {
            int e = k * 256 + tid;            // 0..4095 float4
            int row = e >> 6, c4 = e & 63;
            cpa16(dst + (uint32_t)(row * FSTR + c4 * 4) * 4, src + (size_t)e * 4);
        }
        CP_COMMIT();
    };

    stageF(0);

    const size_t eib = ((size_t)(r * B_ + b) * N_ + i0) * H_ + h;
    const float2 ei0 = g_eli[eib + r0 * H_];
    const float2 ei1 = g_eli[eib + r1 * H_];
    const float2 ei2 = g_eli[eib + r2 * H_];
    const float2 ei3 = g_eli[eib + r3 * H_];

    float racc[2][8][4];
#pragma unroll
    for (int mt = 0; mt < 2; mt++)
#pragma unroll
        for (int nt = 0; nt < 8; nt++)
#pragma unroll
            for (int k = 0; k < 4; k++) racc[mt][nt][k] = 0.f;
    float es0 = 0.f, es1 = 0.f, es2 = 0.f, es3 = 0.f;

    const unsigned* bw0p = bits + r0 * 32;
    const unsigned* bw1p = bits + r1 * 32;
    const unsigned* bw2p = bits + r2 * 32;
    const unsigned* bw3p = bits + r3 * 32;

    for (int jc = 0; jc < 16; jc++) {
        if (jc + 1 < 16) { stageF(jc + 1); CP_WAIT(1); } else { CP_WAIT(0); }
        __syncthreads();                                  // staged F (+bits/Elj) visible
        const float* Fsb = Fs + (jc & 1) * FBUF;

        const unsigned bw0[2] = { bw0p[jc * 2], bw0p[jc * 2 + 1] };
        const unsigned bw1[2] = { bw1p[jc * 2], bw1p[jc * 2 + 1] };
        const unsigned bw2[2] = { bw2p[jc * 2], bw2p[jc * 2 + 1] };
        const unsigned bw3[2] = { bw3p[jc * 2], bw3p[jc * 2 + 1] };

#pragma unroll
        for (int kc = 0; kc < 8; kc++) {                  // 8 k-slabs of 8 j's
            const int jb = kc * 8;
            const unsigned wr0 = bw0[kc >> 2], wr1 = bw1[kc >> 2];
            const unsigned wr2 = bw2[kc >> 2], wr3 = bw3[kc >> 2];
            const int sl = (jb & 31) + t;

            const float2 ejA = Elj[(jc * 64 + jb + t) * H_ + h];
            const float2 ejB = Elj[(jc * 64 + jb + t + 4) * H_ + h];

            // exp(leaky_relu(li+lj)) = max(e^li*e^lj, e^(a li)*e^(a lj))
            float e0A = fmaxf(ei0.x * ejA.x, ei0.y * ejA.y);
            float e1A = fmaxf(ei1.x * ejA.x, ei1.y * ejA.y);
            float e2A = fmaxf(ei2.x * ejA.x, ei2.y * ejA.y);
            float e3A = fmaxf(ei3.x * ejA.x, ei3.y * ejA.y);
            float e0B = fmaxf(ei0.x * ejB.x, ei0.y * ejB.y);
            float e1B = fmaxf(ei1.x * ejB.x, ei1.y * ejB.y);
            float e2B = fmaxf(ei2.x * ejB.x, ei2.y * ejB.y);
            float e3B = fmaxf(ei3.x * ejB.x, ei3.y * ejB.y);
            e0A = ((wr0 >> sl) & 1u)       ? e0A : 0.f;
            e1A = ((wr1 >> sl) & 1u)       ? e1A : 0.f;
            e2A = ((wr2 >> sl) & 1u)       ? e2A : 0.f;
            e3A = ((wr3 >> sl) & 1u)       ? e3A : 0.f;
            e0B = ((wr0 >> (sl + 4)) & 1u) ? e0B : 0.f;
            e1B = ((wr1 >> (sl + 4)) & 1u) ? e1B : 0.f;
            e2B = ((wr2 >> (sl + 4)) & 1u) ? e2B : 0.f;
            e3B = ((wr3 >> (sl + 4)) & 1u) ? e3B : 0.f;

            const unsigned a00 = cvt_tf32(e0A), a01 = cvt_tf32(e1A);
            const unsigned a02 = cvt_tf32(e0B), a03 = cvt_tf32(e1B);
            const unsigned a10 = cvt_tf32(e2A), a11 = cvt_tf32(e3A);
            const unsigned a12 = cvt_tf32(e2B), a13 = cvt_tf32(e3B);
            es0 += __uint_as_float(a00) + __uint_as_float(a02);
            es1 += __uint_as_float(a01) + __uint_as_float(a03);
            es2 += __uint_as_float(a10) + __uint_as_float(a12);
            es3 += __uint_as_float(a11) + __uint_as_float(a13);

            const float* brow0 = Fsb + (jb + t) * FSTR + nb + g;
            const float* brow1 = brow0 + 4 * FSTR;
#pragma unroll
            for (int nt = 0; nt < 8; nt++) {
                unsigned b0 = __float_as_uint(brow0[nt * 8]);
                unsigned b1 = __float_as_uint(brow1[nt * 8]);
                mma_tf32(racc[0][nt], a00, a01, a02, a03, b0, b1);
                mma_tf32(racc[1][nt], a10, a11, a12, a13, b0, b1);
            }
        }
        __syncthreads();                                  // buffer free for restage
    }

    // row sums: reduce across the 4 lanes of each group
    es0 += __shfl_xor_sync(0xffffffffu, es0, 1);
    es0 += __shfl_xor_sync(0xffffffffu, es0, 2);
    es1 += __shfl_xor_sync(0xffffffffu, es1, 1);
    es1 += __shfl_xor_sync(0xffffffffu, es1, 2);
    es2 += __shfl_xor_sync(0xffffffffu, es2, 1);
    es2 += __shfl_xor_sync(0xffffffffu, es2, 2);
    es3 += __shfl_xor_sync(0xffffffffu, es3, 1);
    es3 += __shfl_xor_sync(0xffffffffu, es3, 2);
    const float inv0 = es0 > 0.f ? 1.0f / es0 : 0.f;
    const float inv1 = es1 > 0.f ? 1.0f / es1 : 0.f;
    const float inv2 = es2 > 0.f ? 1.0f / es2 : 0.f;
    const float inv3 = es3 > 0.f ? 1.0f / es3 : 0.f;

    // write normalized per-relation partial: g_part[r][b][i][c]
    float* P = g_part + (size_t)(r * B_ + b) * N_ * COUT;
    float* o0 = P + (size_t)(i0 + r0) * COUT + nb + 2 * t;
    float* o1 = P + (size_t)(i0 + r1) * COUT + nb + 2 * t;
    float* o2 = P + (size_t)(i0 + r2) * COUT + nb + 2 * t;
    float* o3 = P + (size_t)(i0 + r3) * COUT + nb + 2 * t;
#pragma unroll
    for (int nt = 0; nt < 8; nt++) {
        *(float2*)(o0 + nt * 8) = make_float2(racc[0][nt][0] * inv0, racc[0][nt][1] * inv0);
        *(float2*)(o1 + nt * 8) = make_float2(racc[0][nt][2] * inv1, racc[0][nt][3] * inv1);
        *(float2*)(o2 + nt * 8) = make_float2(racc[1][nt][0] * inv2, racc[1][nt][1] * inv2);
        *(float2*)(o3 + nt * 8) = make_float2(racc[1][nt][2] * inv3, racc[1][nt][3] * inv3);
    }
}

// ---------------------------------------------------------------------------
// Kernel 3: reduce the 4 relation partials into the output.
// ---------------------------------------------------------------------------
__global__ __launch_bounds__(256)
void reduce_kernel(float* __restrict__ out)
{
    const size_t idx = (size_t)blockIdx.x * 256 + threadIdx.x;  // < B*N*COUT/4
    const size_t rstride = (size_t)B_ * N_ * COUT / 4;          // float4 stride per r
    const float4* p = (const float4*)g_part;
    float4 v0 = p[idx];
    float4 v1 = p[idx + rstride];
    float4 v2 = p[idx + 2 * rstride];
    float4 v3 = p[idx + 3 * rstride];
    float4 s;
    s.x = (v0.x + v1.x) + (v2.x + v3.x);
    s.y = (v0.y + v1.y) + (v2.y + v3.y);
    s.z = (v0.z + v1.z) + (v2.z + v3.z);
    s.w = (v0.w + v1.w) + (v2.w + v3.w);
    ((float4*)out)[idx] = s;
}

// ---------------------------------------------------------------------------
extern "C" void kernel_launch(void* const* d_in, const int* in_sizes, int n_in,
                              void* d_out, int out_size)
{
    const float* X   = (const float*)d_in[0];   // node_feats (B,N,CIN)
    const int*   adj = (const int*)  d_in[1];   // adj (B,N,N,R)
    const float* W   = (const float*)d_in[2];   // (R,CIN,COUT)
    const float* a   = (const float*)d_in[3];   // (R,H,2C)
    float* out = (float*)d_out;                 // (B,N,H*C)

    pack_kernel<<<(B_ * N_ * 32) / 256, 256>>>(adj);

    gemm_kernel<<<dim3(N_ / 128, COUT / 128, R_ * B_), 256>>>(X, W, a);

    const int SMEM = (2 * FBUF) * 4 + (N_ * H_) * 8 + (64 * 32) * 4;  // 176128 B
    cudaFuncSetAttribute(attn_kernel, cudaFuncAttributeMaxDynamicSharedMemorySize, SMEM);
    attn_kernel<<<R_ * B_ * 16, 256, SMEM>>>(out);

    reduce_kernel<<<(B_ * N_ * COUT / 4) / 256, 256>>>(out);
}

// round 13
// speedup vs baseline: 1.5793x; 1.5793x over previous
#include <cuda_runtime.h>
#include <cstdint>

#define ALPHA 0.2f

// Problem constants (fixed by the dataset)
#define B_   8
#define N_   1024
#define CIN  256
#define COUT 256
#define R_   4
#define H_   4

// Scratch (static device arrays; no runtime allocation)
__device__ __align__(16) float    g_F   [R_ * B_ * N_ * COUT];  // 32 MB tf32-rounded
__device__ __align__(16) float2   g_eli [R_ * B_ * N_ * H_];
__device__ __align__(16) float2   g_elj [R_ * B_ * N_ * H_];
__device__ __align__(16) unsigned g_bits[B_ * R_ * N_ * 32];    // 4 MB adjacency bitmaps

// ---------------------------------------------------------------------------
// helpers
// ---------------------------------------------------------------------------
__device__ __forceinline__ unsigned cvt_tf32(float f) {
    unsigned u;
    asm("cvt.rna.tf32.f32 %0, %1;" : "=r"(u) : "f"(f));
    return u;
}

__device__ __forceinline__ void mma_tf32(float* c,
                                         unsigned a0, unsigned a1, unsigned a2, unsigned a3,
                                         unsigned b0, unsigned b1) {
    asm volatile("mma.sync.aligned.m16n8k8.row.col.f32.tf32.tf32.f32 "
                 "{%0,%1,%2,%3}, {%4,%5,%6,%7}, {%8,%9}, {%0,%1,%2,%3};"
                 : "+f"(c[0]), "+f"(c[1]), "+f"(c[2]), "+f"(c[3])
                 : "r"(a0), "r"(a1), "r"(a2), "r"(a3), "r"(b0), "r"(b1));
}

__device__ __forceinline__ void cpa16(uint32_t dst, const void* src) {
    asm volatile("cp.async.cg.shared.global [%0], [%1], 16;" :: "r"(dst), "l"(src));
}
#define CP_COMMIT() asm volatile("cp.async.commit_group;")
#define CP_WAIT(n)  asm volatile("cp.async.wait_group %0;" :: "n"(n))

// ---------------------------------------------------------------------------
// Kernel 0: pack adjacency into per-relation bitmasks (reads adj ONCE).
// g_bits layout: [b][r][i][jw]  (jw = j/32)
// ---------------------------------------------------------------------------
__global__ __launch_bounds__(256)
void pack_kernel(const int* __restrict__ adj)
{
    const int idx = blockIdx.x * 256 + threadIdx.x;   // < B*N*32
    const int jw = idx & 31;
    const int i  = (idx >> 5) & (N_ - 1);
    const int b  = idx >> 15;

    const int4* ap = (const int4*)adj + ((size_t)(b * N_ + i) * N_ + jw * 32);
    unsigned w0 = 0, w1 = 0, w2 = 0, w3 = 0;
#pragma unroll 8
    for (int jj = 0; jj < 32; jj++) {
        int4 v = ap[jj];
        w0 |= (unsigned)(v.x != 0) << jj;
        w1 |= (unsigned)(v.y != 0) << jj;
        w2 |= (unsigned)(v.z != 0) << jj;
        w3 |= (unsigned)(v.w != 0) << jj;
    }
    const size_t base = ((size_t)b * R_ * N_ + i) * 32 + jw;
    g_bits[base + (size_t)0 * N_ * 32] = w0;
    g_bits[base + (size_t)1 * N_ * 32] = w1;
    g_bits[base + (size_t)2 * N_ * 32] = w2;
    g_bits[base + (size_t)3 * N_ * 32] = w3;
}

// ---------------------------------------------------------------------------
// Kernel 1: F[r,b] = X[b] @ W[r] via tf32 mma.sync, li/lj fused in epilogue.
// ---------------------------------------------------------------------------
#define PADK 20
#define PADN 136

__global__ __launch_bounds__(256, 2)
void gemm_kernel(const float* __restrict__ X, const float* __restrict__ W,
                 const float* __restrict__ a)
{
    const int rb = blockIdx.z, r = rb >> 3, b = rb & 7;
    const float* Ag = X + (size_t)b * N_ * CIN;
    const float* Bg = W + (size_t)r * CIN * COUT;
    float* out = g_F + (size_t)rb * N_ * COUT;
    const int m0 = blockIdx.x * 128, n0 = blockIdx.y * 128;

    __shared__ float As[2][128 * PADK];
    __shared__ float Bs[2][16 * PADN];

    const int tid = threadIdx.x, warp = tid >> 5, lane = tid & 31;
    const int wm = (warp & 3) * 32, wn = (warp >> 2) * 64;
    const int g = lane >> 2, t = lane & 3;

    const uint32_t sA = (uint32_t)__cvta_generic_to_shared(&As[0][0]);
    const uint32_t sB = (uint32_t)__cvta_generic_to_shared(&Bs[0][0]);

    float acc[2][8][4];
#pragma unroll
    for (int mt = 0; mt < 2; mt++)
#pragma unroll
        for (int nt = 0; nt < 8; nt++)
#pragma unroll
            for (int k = 0; k < 4; k++) acc[mt][nt][k] = 0.f;

    auto stage = [&](int s) {
        const int buf = s & 1, k0 = s * 16;
#pragma unroll
        for (int i = 0; i < 2; i++) {
            int idx = tid * 2 + i;
            int row = idx >> 2, c = idx & 3;
            cpa16(sA + (uint32_t)(buf * (128 * PADK) + row * PADK + c * 4) * 4,
                  Ag + (size_t)(m0 + row) * CIN + k0 + c * 4);
        }
#pragma unroll
        for (int i = 0; i < 2; i++) {
            int idx = tid * 2 + i;
            int row = idx >> 5, c = idx & 31;
            cpa16(sB + (uint32_t)(buf * (16 * PADN) + row * PADN + c * 4) * 4,
                  Bg + (size_t)(k0 + row) * COUT + n0 + c * 4);
        }
        CP_COMMIT();
    };

    stage(0);
    for (int s = 0; s < 16; s++) {
        if (s + 1 < 16) { stage(s + 1); CP_WAIT(1); } else { CP_WAIT(0); }
        __syncthreads();
        const float* Ab = As[s & 1];
        const float* Bb = Bs[s & 1];
#pragma unroll
        for (int kk = 0; kk < 16; kk += 8) {
            unsigned af[2][4], bf[8][2];
#pragma unroll
            for (int mt = 0; mt < 2; mt++) {
                int rowb = wm + mt * 16 + g;
                af[mt][0] = cvt_tf32(Ab[rowb * PADK + kk + t]);
                af[mt][1] = cvt_tf32(Ab[(rowb + 8) * PADK + kk + t]);
                af[mt][2] = cvt_tf32(Ab[rowb * PADK + kk + 4 + t]);
                af[mt][3] = cvt_tf32(Ab[(rowb + 8) * PADK + kk + 4 + t]);
            }
#pragma unroll
            for (int nt = 0; nt < 8; nt++) {
                int col = wn + nt * 8 + g;
                bf[nt][0] = cvt_tf32(Bb[(kk + t) * PADN + col]);
                bf[nt][1] = cvt_tf32(Bb[(kk + 4 + t) * PADN + col]);
            }
#pragma unroll
            for (int mt = 0; mt < 2; mt++)
#pragma unroll
                for (int nt = 0; nt < 8; nt++)
                    mma_tf32(acc[mt][nt], af[mt][0], af[mt][1], af[mt][2], af[mt][3],
                             bf[nt][0], bf[nt][1]);
        }
        __syncthreads();
    }

    // fused li/lj epilogue (warp tile covers head h fully)
    {
        const int h = blockIdx.y * 2 + (warp >> 2);
        const float2* al2 = (const float2*)(a + (size_t)(r * H_ + h) * 128);
        const float2* ar2 = al2 + 32;
#pragma unroll
        for (int mt = 0; mt < 2; mt++) {
            float sliA = 0.f, sliB = 0.f, sljA = 0.f, sljB = 0.f;
#pragma unroll
            for (int nt = 0; nt < 8; nt++) {
                float2 al = al2[nt * 4 + t];
                float2 ar = ar2[nt * 4 + t];
                sliA += acc[mt][nt][0] * al.x + acc[mt][nt][1] * al.y;
                sliB += acc[mt][nt][2] * al.x + acc[mt][nt][3] * al.y;
                sljA += acc[mt][nt][0] * ar.x + acc[mt][nt][1] * ar.y;
                sljB += acc[mt][nt][2] * ar.x + acc[mt][nt][3] * ar.y;
            }
#pragma unroll
            for (int d = 1; d < 4; d <<= 1) {
                sliA += __shfl_xor_sync(0xffffffffu, sliA, d);
                sliB += __shfl_xor_sync(0xffffffffu, sliB, d);
                sljA += __shfl_xor_sync(0xffffffffu, sljA, d);
                sljB += __shfl_xor_sync(0xffffffffu, sljB, d);
            }
            if (t == 0) {
                const int row = m0 + wm + mt * 16 + g;
                const size_t base = ((size_t)(r * B_ + b) * N_ + row) * H_ + h;
                g_eli[base] = make_float2(__expf(sliA), __expf(ALPHA * sliA));
                g_elj[base] = make_float2(__expf(sljA), __expf(ALPHA * sljA));
                g_eli[base + 8 * H_] = make_float2(__expf(sliB), __expf(ALPHA * sliB));
                g_elj[base + 8 * H_] = make_float2(__expf(sljB), __expf(ALPHA * sljB));
            }
        }
    }

    // store F pre-rounded to tf32
#pragma unroll
    for (int mt = 0; mt < 2; mt++) {
        int row = m0 + wm + mt * 16 + g;
#pragma unroll
        for (int nt = 0; nt < 8; nt++) {
            int col = n0 + wn + nt * 8 + 2 * t;
            float2 v0 = make_float2(__uint_as_float(cvt_tf32(acc[mt][nt][0])),
                                    __uint_as_float(cvt_tf32(acc[mt][nt][1])));
            float2 v1 = make_float2(__uint_as_float(cvt_tf32(acc[mt][nt][2])),
                                    __uint_as_float(cvt_tf32(acc[mt][nt][3])));
            *(float2*)(out + (size_t)row * COUT + col) = v0;
            *(float2*)(out + (size_t)(row + 8) * COUT + col) = v1;
        }
    }
}

// ---------------------------------------------------------------------------
// Kernel 2: attention + aggregation, all 4 relations per block (single wave,
// 128 blocks).  256 thr = 8 warps = (mi 0..1) x (h 0..3), warp tile 32i x 64c.
// outacc lives in SMEM (cold, touched per relation) -> ~170 regs, no spills.
// esum computed by an extra "ones-column" MMA -> no FADDs, no shuffles.
// ---------------------------------------------------------------------------
#define FSTR 264            // F smem row stride (floats); 264 % 32 == 8
#define FBUF (64 * FSTR)    // floats per F buffer

__global__ __launch_bounds__(256, 1)
void attn_kernel(float* __restrict__ out)
{
    extern __shared__ float smem[];
    float*    Fs   = smem;                                 // 2 x FBUF floats
    float2*   Elj  = (float2*)(smem + 2 * FBUF);           // 2 bufs x 256 float2
    unsigned* bits = (unsigned*)(smem + 2 * FBUF + 1024);  // 64 x 32 u32 (this r)
    float*    osm  = smem + 2 * FBUF + 1024 + 2048;        // outacc [64][256]

    const uint32_t sF = (uint32_t)__cvta_generic_to_shared(smem);
    const uint32_t sE = sF + (uint32_t)(2 * FBUF) * 4;

    const int tid = threadIdx.x;
    const int b  = blockIdx.x >> 4;                        // 128 blocks = 8 b x 16 tiles
    const int i0 = (blockIdx.x & 15) * 64;

    const int warp = tid >> 5, lane = tid & 31;
    const int h = warp & 3, mi = warp >> 2;                // mi in {0,1}
    const int g = lane >> 2, t = lane & 3;
    const int r0 = mi * 32 + g, r1 = r0 + 8, r2 = r0 + 16, r3 = r0 + 24;
    const int nb = h * 64;
    const unsigned ONE = 0x3f800000u;                      // tf32(1.0)

    for (int r = 0; r < R_; r++) {
        // stage bitmap for this (b,r,i-tile): 8 KB (visible after 1st chunk sync)
        {
            const uint4* bsrc = (const uint4*)(g_bits + (((size_t)b * R_ + r) * N_ + i0) * 32);
            uint4* bdst = (uint4*)bits;
            bdst[tid] = bsrc[tid];
            bdst[256 + tid] = bsrc[256 + tid];
        }

        const float* Fb = g_F + (size_t)(r * B_ + b) * N_ * COUT;
        const char*  Ejb = (const char*)(g_elj + (size_t)(r * B_ + b) * N_ * H_);

        auto stageF = [&](int jc) {
            const int buf = jc & 1;
            const float* src = Fb + (size_t)jc * 64 * COUT;
            const uint32_t dst = sF + (uint32_t)(buf * FBUF) * 4;
#pragma unroll
            for (int k = 0; k < 16; k++) {
                int e = k * 256 + tid;            // 0..4095 float4
                int row = e >> 6, c4 = e & 63;
                cpa16(dst + (uint32_t)(row * FSTR + c4 * 4) * 4, src + (size_t)e * 4);
            }
            if (tid < 128)                         // Elj chunk: 2048 B
                cpa16(sE + (uint32_t)buf * 2048 + tid * 16,
                      Ejb + (size_t)jc * 2048 + tid * 16);
            CP_COMMIT();
        };

        stageF(0);

        const size_t eib = ((size_t)(r * B_ + b) * N_ + i0) * H_ + h;
        const float2 ei0 = g_eli[eib + r0 * H_];
        const float2 ei1 = g_eli[eib + r1 * H_];
        const float2 ei2 = g_eli[eib + r2 * H_];
        const float2 ei3 = g_eli[eib + r3 * H_];

        float racc[2][8][4], racc_e[2][4];
#pragma unroll
        for (int mt = 0; mt < 2; mt++) {
#pragma unroll
            for (int nt = 0; nt < 8; nt++)
#pragma unroll
                for (int k = 0; k < 4; k++) racc[mt][nt][k] = 0.f;
#pragma unroll
            for (int k = 0; k < 4; k++) racc_e[mt][k] = 0.f;
        }

        const unsigned* bw0p = bits + r0 * 32;
        const unsigned* bw1p = bits + r1 * 32;
        const unsigned* bw2p = bits + r2 * 32;
        const unsigned* bw3p = bits + r3 * 32;

        for (int jc = 0; jc < 16; jc++) {
            if (jc + 1 < 16) { stageF(jc + 1); CP_WAIT(1); } else { CP_WAIT(0); }
            __syncthreads();                               // F/Elj chunk + bits visible
            const float*  Fsb = Fs + (jc & 1) * FBUF;
            const float2* Ecb = Elj + (jc & 1) * 256;

            const unsigned bw0[2] = { bw0p[jc * 2], bw0p[jc * 2 + 1] };
            const unsigned bw1[2] = { bw1p[jc * 2], bw1p[jc * 2 + 1] };
            const unsigned bw2[2] = { bw2p[jc * 2], bw2p[jc * 2 + 1] };
            const unsigned bw3[2] = { bw3p[jc * 2], bw3p[jc * 2 + 1] };

#pragma unroll
            for (int kc = 0; kc < 8; kc++) {               // 8 k-slabs of 8 j's
                const int jb = kc * 8;
                const unsigned wr0 = bw0[kc >> 2], wr1 = bw1[kc >> 2];
                const unsigned wr2 = bw2[kc >> 2], wr3 = bw3[kc >> 2];
                const int sl = (jb & 31) + t;

                const float2 ejA = Ecb[(jb + t) * H_ + h];
                const float2 ejB = Ecb[(jb + t + 4) * H_ + h];

                // exp(leaky_relu(li+lj)) = max(e^li*e^lj, e^(a li)*e^(a lj))
                float e0A = fmaxf(ei0.x * ejA.x, ei0.y * ejA.y);
                float e1A = fmaxf(ei1.x * ejA.x, ei1.y * ejA.y);
                float e2A = fmaxf(ei2.x * ejA.x, ei2.y * ejA.y);
                float e3A = fmaxf(ei3.x * ejA.x, ei3.y * ejA.y);
                float e0B = fmaxf(ei0.x * ejB.x, ei0.y * ejB.y);
                float e1B = fmaxf(ei1.x * ejB.x, ei1.y * ejB.y);
                float e2B = fmaxf(ei2.x * ejB.x, ei2.y * ejB.y);
                float e3B = fmaxf(ei3.x * ejB.x, ei3.y * ejB.y);
                e0A = ((wr0 >> sl) & 1u)       ? e0A : 0.f;
                e1A = ((wr1 >> sl) & 1u)       ? e1A : 0.f;
                e2A = ((wr2 >> sl) & 1u)       ? e2A : 0.f;
                e3A = ((wr3 >> sl) & 1u)       ? e3A : 0.f;
                e0B = ((wr0 >> (sl + 4)) & 1u) ? e0B : 0.f;
                e1B = ((wr1 >> (sl + 4)) & 1u) ? e1B : 0.f;
                e2B = ((wr2 >> (sl + 4)) & 1u) ? e2B : 0.f;
                e3B = ((wr3 >> (sl + 4)) & 1u) ? e3B : 0.f;

                const unsigned a00 = cvt_tf32(e0A), a01 = cvt_tf32(e1A);
                const unsigned a02 = cvt_tf32(e0B), a03 = cvt_tf32(e1B);
                const unsigned a10 = cvt_tf32(e2A), a11 = cvt_tf32(e3A);
                const unsigned a12 = cvt_tf32(e2B), a13 = cvt_tf32(e3B);

                // ones-column MMA accumulates the row sums (esum) in fp32
                mma_tf32(racc_e[0], a00, a01, a02, a03, ONE, ONE);
                mma_tf32(racc_e[1], a10, a11, a12, a13, ONE, ONE);

                const float* brow0 = Fsb + (jb + t) * FSTR + nb + g;
                const float* brow1 = brow0 + 4 * FSTR;
#pragma unroll
                for (int nt = 0; nt < 8; nt++) {
                    unsigned b0 = __float_as_uint(brow0[nt * 8]);
                    unsigned b1 = __float_as_uint(brow1[nt * 8]);
                    mma_tf32(racc[0][nt], a00, a01, a02, a03, b0, b1);
                    mma_tf32(racc[1][nt], a10, a11, a12, a13, b0, b1);
                }
            }
            __syncthreads();                               // buffer free for restage
        }

        // every output column of the ones-MMA equals the row sum
        const float es0 = racc_e[0][0], es1 = racc_e[0][2];
        const float es2 = racc_e[1][0], es3 = racc_e[1][2];
        const float inv0 = es0 > 0.f ? 1.0f / es0 : 0.f;
        const float inv1 = es1 > 0.f ? 1.0f / es1 : 0.f;
        const float inv2 = es2 > 0.f ? 1.0f / es2 : 0.f;
        const float inv3 = es3 > 0.f ? 1.0f / es3 : 0.f;

        // accumulate normalized relation result into smem outacc (own slots)
#pragma unroll
        for (int mt = 0; mt < 2; mt++) {
            const float iva = mt ? inv2 : inv0;
            const float ivb = mt ? inv3 : inv1;
#pragma unroll
            for (int nt = 0; nt < 8; nt++) {
                const int s = (mt * 8 + nt) * 4;
                const float v0 = racc[mt][nt][0] * iva, v1 = racc[mt][nt][1] * iva;
                const float v2 = racc[mt][nt][2] * ivb, v3 = racc[mt][nt][3] * ivb;
                if (r == 0) {
                    osm[(s + 0) * 256 + tid] = v0;
                    osm[(s + 1) * 256 + tid] = v1;
                    osm[(s + 2) * 256 + tid] = v2;
                    osm[(s + 3) * 256 + tid] = v3;
                } else {
                    osm[(s + 0) * 256 + tid] += v0;
                    osm[(s + 1) * 256 + tid] += v1;
                    osm[(s + 2) * 256 + tid] += v2;
                    osm[(s + 3) * 256 + tid] += v3;
                }
            }
        }
    }

    // store: out[b, i, h*64 + c]
    float* o0 = out + ((size_t)b * N_ + i0 + r0) * COUT + nb + 2 * t;
    float* o1 = out + ((size_t)b * N_ + i0 + r1) * COUT + nb + 2 * t;
    float* o2 = out + ((size_t)b * N_ + i0 + r2) * COUT + nb + 2 * t;
    float* o3 = out + ((size_t)b * N_ + i0 + r3) * COUT + nb + 2 * t;
#pragma unroll
    for (int nt = 0; nt < 8; nt++) {
        const int s0 = nt * 4, s1 = (8 + nt) * 4;
        *(float2*)(o0 + nt * 8) = make_float2(osm[(s0 + 0) * 256 + tid], osm[(s0 + 1) * 256 + tid]);
        *(float2*)(o1 + nt * 8) = make_float2(osm[(s0 + 2) * 256 + tid], osm[(s0 + 3) * 256 + tid]);
        *(float2*)(o2 + nt * 8) = make_float2(osm[(s1 + 0) * 256 + tid], osm[(s1 + 1) * 256 + tid]);
        *(float2*)(o3 + nt * 8) = make_float2(osm[(s1 + 2) * 256 + tid], osm[(s1 + 3) * 256 + tid]);
    }
}

// ---------------------------------------------------------------------------
extern "C" void kernel_launch(void* const* d_in, const int* in_sizes, int n_in,
                              void* d_out, int out_size)
{
    const float* X   = (const float*)d_in[0];   // node_feats (B,N,CIN)
    const int*   adj = (const int*)  d_in[1];   // adj (B,N,N,R)
    const float* W   = (const float*)d_in[2];   // (R,CIN,COUT)
    const float* a   = (const float*)d_in[3];   // (R,H,2C)
    float* out = (float*)d_out;                 // (B,N,H*C)

    pack_kernel<<<(B_ * N_ * 32) / 256, 256>>>(adj);

    gemm_kernel<<<dim3(N_ / 128, COUT / 128, R_ * B_), 256>>>(X, W, a);

    // smem: 2*FBUF (F) + 1024 (Elj) + 2048 (bits) + 16384 (outacc) floats
    const int SMEM = (2 * FBUF + 1024 + 2048 + 16384) * 4;   // 212,992 B
    cudaFuncSetAttribute(attn_kernel, cudaFuncAttributeMaxDynamicSharedMemorySize, SMEM);
    attn_kernel<<<(B_ * N_) / 64, 256, SMEM>>>(out);
}

// round 14
// speedup vs baseline: 1.6086x; 1.0185x over previous
#include <cuda_runtime.h>
#include <cstdint>

#define ALPHA 0.2f

// Problem constants (fixed by the dataset)
#define B_   8
#define N_   1024
#define CIN  256
#define COUT 256
#define R_   4
#define H_   4

// Scratch (static device arrays; no runtime allocation)
__device__ __align__(16) float    g_F   [R_ * B_ * N_ * COUT];  // 32 MB tf32-rounded
__device__ __align__(16) float2   g_eli [R_ * B_ * N_ * H_];
__device__ __align__(16) float2   g_elj [R_ * B_ * N_ * H_];
__device__ __align__(16) unsigned g_bits[B_ * R_ * N_ * 32];    // 4 MB adjacency bitmaps

// ---------------------------------------------------------------------------
// helpers
// ---------------------------------------------------------------------------
__device__ __forceinline__ unsigned cvt_tf32(float f) {
    unsigned u;
    asm("cvt.rna.tf32.f32 %0, %1;" : "=r"(u) : "f"(f));
    return u;
}

__device__ __forceinline__ void mma_tf32(float* c,
                                         unsigned a0, unsigned a1, unsigned a2, unsigned a3,
                                         unsigned b0, unsigned b1) {
    asm volatile("mma.sync.aligned.m16n8k8.row.col.f32.tf32.tf32.f32 "
                 "{%0,%1,%2,%3}, {%4,%5,%6,%7}, {%8,%9}, {%0,%1,%2,%3};"
                 : "+f"(c[0]), "+f"(c[1]), "+f"(c[2]), "+f"(c[3])
                 : "r"(a0), "r"(a1), "r"(a2), "r"(a3), "r"(b0), "r"(b1));
}

__device__ __forceinline__ void cpa16(uint32_t dst, const void* src) {
    asm volatile("cp.async.cg.shared.global [%0], [%1], 16;" :: "r"(dst), "l"(src));
}
#define CP_COMMIT() asm volatile("cp.async.commit_group;")
#define CP_WAIT(n)  asm volatile("cp.async.wait_group %0;" :: "n"(n))

// ---------------------------------------------------------------------------
// Kernel 0: pack adjacency via warp ballots.  One warp per (b,i,jw):
// each lane reads one int4 (all 4 relations for one j), 4 ballots produce the
// four 32-bit masks.  g_bits layout: [b][r][i][jw]
// ---------------------------------------------------------------------------
__global__ __launch_bounds__(256)
void pack_kernel(const int* __restrict__ adj)
{
    const int gw   = (blockIdx.x * 256 + threadIdx.x) >> 5;  // < B*N*32
    const int lane = threadIdx.x & 31;
    const int jw = gw & 31;
    const int i  = (gw >> 5) & (N_ - 1);
    const int b  = gw >> 15;

    const int4 v = ((const int4*)adj)[(size_t)(b * N_ + i) * N_ + jw * 32 + lane];
    const unsigned m0 = __ballot_sync(0xffffffffu, v.x != 0);
    const unsigned m1 = __ballot_sync(0xffffffffu, v.y != 0);
    const unsigned m2 = __ballot_sync(0xffffffffu, v.z != 0);
    const unsigned m3 = __ballot_sync(0xffffffffu, v.w != 0);
    if (lane == 0) {
        const size_t base = ((size_t)b * R_ * N_ + i) * 32 + jw;
        g_bits[base]                      = m0;
        g_bits[base + (size_t)N_ * 32]    = m1;
        g_bits[base + (size_t)2 * N_ * 32] = m2;
        g_bits[base + (size_t)3 * N_ * 32] = m3;
    }
}

// ---------------------------------------------------------------------------
// Kernel 1: F[r,b] = X[b] @ W[r] via tf32 mma.sync, li/lj fused in epilogue.
// ---------------------------------------------------------------------------
#define PADK 20
#define PADN 136

__global__ __launch_bounds__(256, 2)
void gemm_kernel(const float* __restrict__ X, const float* __restrict__ W,
                 const float* __restrict__ a)
{
    const int rb = blockIdx.z, r = rb >> 3, b = rb & 7;
    const float* Ag = X + (size_t)b * N_ * CIN;
    const float* Bg = W + (size_t)r * CIN * COUT;
    float* out = g_F + (size_t)rb * N_ * COUT;
    const int m0 = blockIdx.x * 128, n0 = blockIdx.y * 128;

    __shared__ float As[2][128 * PADK];
    __shared__ float Bs[2][16 * PADN];

    const int tid = threadIdx.x, warp = tid >> 5, lane = tid & 31;
    const int wm = (warp & 3) * 32, wn = (warp >> 2) * 64;
    const int g = lane >> 2, t = lane & 3;

    const uint32_t sA = (uint32_t)__cvta_generic_to_shared(&As[0][0]);
    const uint32_t sB = (uint32_t)__cvta_generic_to_shared(&Bs[0][0]);

    float acc[2][8][4];
#pragma unroll
    for (int mt = 0; mt < 2; mt++)
#pragma unroll
        for (int nt = 0; nt < 8; nt++)
#pragma unroll
            for (int k = 0; k < 4; k++) acc[mt][nt][k] = 0.f;

    auto stage = [&](int s) {
        const int buf = s & 1, k0 = s * 16;
#pragma unroll
        for (int i = 0; i < 2; i++) {
            int idx = tid * 2 + i;
            int row = idx >> 2, c = idx & 3;
            cpa16(sA + (uint32_t)(buf * (128 * PADK) + row * PADK + c * 4) * 4,
                  Ag + (size_t)(m0 + row) * CIN + k0 + c * 4);
        }
#pragma unroll
        for (int i = 0; i < 2; i++) {
            int idx = tid * 2 + i;
            int row = idx >> 5, c = idx & 31;
            cpa16(sB + (uint32_t)(buf * (16 * PADN) + row * PADN + c * 4) * 4,
                  Bg + (size_t)(k0 + row) * COUT + n0 + c * 4);
        }
        CP_COMMIT();
    };

    stage(0);
    for (int s = 0; s < 16; s++) {
        if (s + 1 < 16) { stage(s + 1); CP_WAIT(1); } else { CP_WAIT(0); }
        __syncthreads();
        const float* Ab = As[s & 1];
        const float* Bb = Bs[s & 1];
#pragma unroll
        for (int kk = 0; kk < 16; kk += 8) {
            unsigned af[2][4], bf[8][2];
#pragma unroll
            for (int mt = 0; mt < 2; mt++) {
                int rowb = wm + mt * 16 + g;
                af[mt][0] = cvt_tf32(Ab[rowb * PADK + kk + t]);
                af[mt][1] = cvt_tf32(Ab[(rowb + 8) * PADK + kk + t]);
                af[mt][2] = cvt_tf32(Ab[rowb * PADK + kk + 4 + t]);
                af[mt][3] = cvt_tf32(Ab[(rowb + 8) * PADK + kk + 4 + t]);
            }
#pragma unroll
            for (int nt = 0; nt < 8; nt++) {
                int col = wn + nt * 8 + g;
                bf[nt][0] = cvt_tf32(Bb[(kk + t) * PADN + col]);
                bf[nt][1] = cvt_tf32(Bb[(kk + 4 + t) * PADN + col]);
            }
#pragma unroll
            for (int mt = 0; mt < 2; mt++)
#pragma unroll
                for (int nt = 0; nt < 8; nt++)
                    mma_tf32(acc[mt][nt], af[mt][0], af[mt][1], af[mt][2], af[mt][3],
                             bf[nt][0], bf[nt][1]);
        }
        __syncthreads();
    }

    // fused li/lj epilogue (warp tile covers head h fully)
    {
        const int h = blockIdx.y * 2 + (warp >> 2);
        const float2* al2 = (const float2*)(a + (size_t)(r * H_ + h) * 128);
        const float2* ar2 = al2 + 32;
#pragma unroll
        for (int mt = 0; mt < 2; mt++) {
            float sliA = 0.f, sliB = 0.f, sljA = 0.f, sljB = 0.f;
#pragma unroll
            for (int nt = 0; nt < 8; nt++) {
                float2 al = al2[nt * 4 + t];
                float2 ar = ar2[nt * 4 + t];
                sliA += acc[mt][nt][0] * al.x + acc[mt][nt][1] * al.y;
                sliB += acc[mt][nt][2] * al.x + acc[mt][nt][3] * al.y;
                sljA += acc[mt][nt][0] * ar.x + acc[mt][nt][1] * ar.y;
                sljB += acc[mt][nt][2] * ar.x + acc[mt][nt][3] * ar.y;
            }
#pragma unroll
            for (int d = 1; d < 4; d <<= 1) {
                sliA += __shfl_xor_sync(0xffffffffu, sliA, d);
                sliB += __shfl_xor_sync(0xffffffffu, sliB, d);
                sljA += __shfl_xor_sync(0xffffffffu, sljA, d);
                sljB += __shfl_xor_sync(0xffffffffu, sljB, d);
            }
            if (t == 0) {
                const int row = m0 + wm + mt * 16 + g;
                const size_t base = ((size_t)(r * B_ + b) * N_ + row) * H_ + h;
                g_eli[base] = make_float2(__expf(sliA), __expf(ALPHA * sliA));
                g_elj[base] = make_float2(__expf(sljA), __expf(ALPHA * sljA));
                g_eli[base + 8 * H_] = make_float2(__expf(sliB), __expf(ALPHA * sliB));
                g_elj[base + 8 * H_] = make_float2(__expf(sljB), __expf(ALPHA * sljB));
            }
        }
    }

    // store F pre-rounded to tf32
#pragma unroll
    for (int mt = 0; mt < 2; mt++) {
        int row = m0 + wm + mt * 16 + g;
#pragma unroll
        for (int nt = 0; nt < 8; nt++) {
            int col = n0 + wn + nt * 8 + 2 * t;
            float2 v0 = make_float2(__uint_as_float(cvt_tf32(acc[mt][nt][0])),
                                    __uint_as_float(cvt_tf32(acc[mt][nt][1])));
            float2 v1 = make_float2(__uint_as_float(cvt_tf32(acc[mt][nt][2])),
                                    __uint_as_float(cvt_tf32(acc[mt][nt][3])));
            *(float2*)(out + (size_t)row * COUT + col) = v0;
            *(float2*)(out + (size_t)(row + 8) * COUT + col) = v1;
        }
    }
}

// ---------------------------------------------------------------------------
// Kernel 2: attention + aggregation, channel-split for 2 blocks/SM.
// Grid 256 = b(8) x itile(16) x chalf(2); block = 64 i-rows x 128 channels.
// 256 thr = 8 warps = (mi 0..3) x (hh 0..1), warp tile 16i x 64c.
// osm in smem; esum via ones-column MMA; all 256 blocks co-resident (1 wave).
// ---------------------------------------------------------------------------
#define FSTR2 136            // F smem row stride (floats); 136 % 32 == 8
#define FBUF2 (64 * FSTR2)   // 8704 floats per F buffer

__global__ __launch_bounds__(256, 2)
void attn_kernel(float* __restrict__ out)
{
    extern __shared__ float smem[];
    float*    Fs   = smem;                                  // 2 x FBUF2
    float2*   Elj  = (float2*)(smem + 2 * FBUF2);           // 2 bufs x 64 x 2 float2
    unsigned* bits = (unsigned*)(smem + 2 * FBUF2 + 512);   // 64 x 32 u32 (this r)
    float*    osm  = smem + 2 * FBUF2 + 512 + 2048;         // outacc [32 slots][256]

    const uint32_t sF = (uint32_t)__cvta_generic_to_shared(smem);
    const uint32_t sE = sF + (uint32_t)(2 * FBUF2) * 4;

    const int tid = threadIdx.x;
    const int chalf = blockIdx.x & 1;
    const int i0 = ((blockIdx.x >> 1) & 15) * 64;
    const int b  = blockIdx.x >> 5;
    const int ch0 = chalf * 128;

    const int warp = tid >> 5, lane = tid & 31;
    const int hh = warp & 1, mi = warp >> 1;                // mi 0..3, hh 0..1
    const int h = chalf * 2 + hh;
    const int g = lane >> 2, t = lane & 3;
    const int r0 = mi * 16 + g, r1 = r0 + 8;                // local output rows
    const int nb2 = hh * 64;
    const unsigned ONE = 0x3f800000u;                       // tf32(1.0)

    for (int r = 0; r < R_; r++) {
        // stage bitmap for this (b,r,i-tile): 8 KB (visible after 1st chunk sync)
        {
            const uint4* bsrc = (const uint4*)(g_bits + (((size_t)b * R_ + r) * N_ + i0) * 32);
            uint4* bdst = (uint4*)bits;
            bdst[tid] = bsrc[tid];
            bdst[256 + tid] = bsrc[256 + tid];
        }

        const float* Fb  = g_F + (size_t)(r * B_ + b) * N_ * COUT;
        const char*  Ejb = (const char*)(g_elj + (size_t)(r * B_ + b) * N_ * H_);

        auto stageF = [&](int jc) {
            const int buf = jc & 1;
            const float* src = Fb + (size_t)jc * 64 * COUT + ch0;
            const uint32_t dst = sF + (uint32_t)(buf * FBUF2) * 4;
#pragma unroll
            for (int k = 0; k < 8; k++) {
                int e = k * 256 + tid;            // 0..2047 float4
                int row = e >> 5, c4 = e & 31;
                cpa16(dst + (uint32_t)(row * FSTR2 + c4 * 4) * 4,
                      src + (size_t)row * COUT + c4 * 4);
            }
            if (tid < 64)                          // Elj: 2 heads x 64 j = 1 KB
                cpa16(sE + (uint32_t)buf * 1024 + tid * 16,
                      Ejb + (size_t)(jc * 64 + tid) * 32 + chalf * 16);
            CP_COMMIT();
        };

        stageF(0);

        const size_t eib = ((size_t)(r * B_ + b) * N_ + i0) * H_ + h;
        const float2 ei0 = g_eli[eib + r0 * H_];
        const float2 ei1 = g_eli[eib + r1 * H_];

        float racc[8][4], racc_e[4];
#pragma unroll
        for (int nt = 0; nt < 8; nt++)
#pragma unroll
            for (int k = 0; k < 4; k++) racc[nt][k] = 0.f;
#pragma unroll
        for (int k = 0; k < 4; k++) racc_e[k] = 0.f;

        const unsigned* bw0p = bits + r0 * 32;
        const unsigned* bw1p = bits + r1 * 32;

        for (int jc = 0; jc < 16; jc++) {
            if (jc + 1 < 16) { stageF(jc + 1); CP_WAIT(1); } else { CP_WAIT(0); }
            __syncthreads();                               // F/Elj chunk + bits visible
            const float*  Fsb = Fs + (jc & 1) * FBUF2;
            const float2* Ecb = Elj + (jc & 1) * 128;

            const unsigned bwA[2] = { bw0p[jc * 2], bw0p[jc * 2 + 1] };
            const unsigned bwB[2] = { bw1p[jc * 2], bw1p[jc * 2 + 1] };

#pragma unroll
            for (int kc = 0; kc < 8; kc++) {               // 8 k-slabs of 8 j's
                const int jb = kc * 8;
                const unsigned wr0 = bwA[kc >> 2], wr1 = bwB[kc >> 2];
                const int sl = (jb & 31) + t;

                const float2 ejA = Ecb[(jb + t) * 2 + hh];
                const float2 ejB = Ecb[(jb + t + 4) * 2 + hh];

                // exp(leaky_relu(li+lj)) = max(e^li*e^lj, e^(a li)*e^(a lj))
                float e0A = fmaxf(ei0.x * ejA.x, ei0.y * ejA.y);
                float e1A = fmaxf(ei1.x * ejA.x, ei1.y * ejA.y);
                float e0B = fmaxf(ei0.x * ejB.x, ei0.y * ejB.y);
                float e1B = fmaxf(ei1.x * ejB.x, ei1.y * ejB.y);
                e0A = ((wr0 >> sl) & 1u)       ? e0A : 0.f;
                e1A = ((wr1 >> sl) & 1u)       ? e1A : 0.f;
                e0B = ((wr0 >> (sl + 4)) & 1u) ? e0B : 0.f;
                e1B = ((wr1 >> (sl + 4)) & 1u) ? e1B : 0.f;

                const unsigned a0 = cvt_tf32(e0A), a1 = cvt_tf32(e1A);
                const unsigned a2 = cvt_tf32(e0B), a3 = cvt_tf32(e1B);

                // ones-column MMA accumulates the row sums (esum) in fp32
                mma_tf32(racc_e, a0, a1, a2, a3, ONE, ONE);

                const float* brow0 = Fsb + (jb + t) * FSTR2 + nb2 + g;
                const float* brow1 = brow0 + 4 * FSTR2;
#pragma unroll
                for (int nt = 0; nt < 8; nt++) {
                    unsigned b0 = __float_as_uint(brow0[nt * 8]);
                    unsigned b1 = __float_as_uint(brow1[nt * 8]);
                    mma_tf32(racc[nt], a0, a1, a2, a3, b0, b1);
                }
            }
            __syncthreads();                               // buffer free for restage
        }

        // every output column of the ones-MMA equals the row sum
        const float es0 = racc_e[0], es1 = racc_e[2];
        const float inv0 = es0 > 0.f ? 1.0f / es0 : 0.f;
        const float inv1 = es1 > 0.f ? 1.0f / es1 : 0.f;

        // accumulate normalized relation result into smem outacc (own slots)
#pragma unroll
        for (int nt = 0; nt < 8; nt++) {
            const int s = nt * 4;
            const float v0 = racc[nt][0] * inv0, v1 = racc[nt][1] * inv0;
            const float v2 = racc[nt][2] * inv1, v3 = racc[nt][3] * inv1;
            if (r == 0) {
                osm[(s + 0) * 256 + tid] = v0;
                osm[(s + 1) * 256 + tid] = v1;
                osm[(s + 2) * 256 + tid] = v2;
                osm[(s + 3) * 256 + tid] = v3;
            } else {
                osm[(s + 0) * 256 + tid] += v0;
                osm[(s + 1) * 256 + tid] += v1;
                osm[(s + 2) * 256 + tid] += v2;
                osm[(s + 3) * 256 + tid] += v3;
            }
        }
    }

    // store: out[b, i, ch0 + hh*64 + c]
    float* o0 = out + ((size_t)b * N_ + i0 + r0) * COUT + ch0 + nb2 + 2 * t;
    float* o1 = out + ((size_t)b * N_ + i0 + r1) * COUT + ch0 + nb2 + 2 * t;
#pragma unroll
    for (int nt = 0; nt < 8; nt++) {
        const int s = nt * 4;
        *(float2*)(o0 + nt * 8) = make_float2(osm[(s + 0) * 256 + tid], osm[(s + 1) * 256 + tid]);
        *(float2*)(o1 + nt * 8) = make_float2(osm[(s + 2) * 256 + tid], osm[(s + 3) * 256 + tid]);
    }
}

// ---------------------------------------------------------------------------
extern "C" void kernel_launch(void* const* d_in, const int* in_sizes, int n_in,
                              void* d_out, int out_size)
{
    const float* X   = (const float*)d_in[0];   // node_feats (B,N,CIN)
    const int*   adj = (const int*)  d_in[1];   // adj (B,N,N,R)
    const float* W   = (const float*)d_in[2];   // (R,CIN,COUT)
    const float* a   = (const float*)d_in[3];   // (R,H,2C)
    float* out = (float*)d_out;                 // (B,N,H*C)

    pack_kernel<<<(B_ * N_ * 32 * 32) / 256, 256>>>(adj);

    gemm_kernel<<<dim3(N_ / 128, COUT / 128, R_ * B_), 256>>>(X, W, a);

    // smem: 2*FBUF2 (F) + 512 (Elj) + 2048 (bits) + 8192 (osm) floats
    const int SMEM = (2 * FBUF2 + 512 + 2048 + 8192) * 4;   // 112,640 B
    cudaFuncSetAttribute(attn_kernel, cudaFuncAttributeMaxDynamicSharedMemorySize, SMEM);
    attn_kernel<<<B_ * 16 * 2, 256, SMEM>>>(out);
}